// round 15
// baseline (speedup 1.0000x reference)
#include <cuda_runtime.h>

// ---------------------------------------------------------------------------
// WaveletEncoder: 2-level Haar wavedec2 -> bilinear(antialias) resize to 8x8
// -> stack 7 maps -> [B,64,7] @ W[7,256] + b.
//
// All-linear separable pipeline; axes commute; triangle antialias resize
// weight is linear within blocks of K/2 samples => per-block (sum, moment).
//
// FINAL (R15, converged): kernel time == measured read floor (268MB at the
// chip's sustained ~5.4TB/s; 100.7% of floor). Grid (16,64), one 64-row unit
// per block, flat fully-unrolled LDG.128 quads; 6 H-axis accumulators
// {s1e,s1o,m1e,m1o,s1h,m1h}; exact derived level-2 moments:
//   m2=(m1e+(m1o-s1o))/2, m2h=(m1e-(m1o-s1o))/2, s2h=s1e-s1o, s2=s1.
// W-axis Haar intra-thread -> 16 W-partials/chunk -> 16-lane butterfly ->
// smem -> 256-thread coefficient combine -> V[imgb][8][32] (streaming store).
// The last FOUR arrivals per image (monotonic atomic counter, replay-safe)
// finish the image in parallel: ranks 12-14 spin briefly until all 16
// arrivals, then each computes Y redundantly (bitwise identical) and writes
// its 16 of the 64 output positions. Fully deterministic output.
// ---------------------------------------------------------------------------

#define FULLMASK 0xffffffffu

__device__ float g_V[64u * 16u * 8u * 32u];  // 1 MB [imgb][8 mtH][32 z]
__device__ unsigned g_ctr[64];               // per-image arrival counters

static __device__ __forceinline__ void resize_ab(int o, int t, float K,
                                                 float invK, float fold,
                                                 float &a, float &b) {
    float tot = K * ((o == 0 || o == 7) ? 0.875f : 1.0f);
    float sf = (o + 0.5f) * K - 0.5f;
    float i0 = t * (K * 0.5f);
    float w0 = fmaxf(0.f, 1.f - fabsf(sf - i0) * invK);
    float w1 = fmaxf(0.f, 1.f - fabsf(sf - (i0 + 1.f)) * invK);
    float s = fold / tot;
    a = w0 * s;
    b = (w1 - w0) * s;
}

static __device__ __forceinline__ void fill_tables(int tid, float *tA512,
                                                   float *tB512, float *tA256,
                                                   float *tB256) {
    if (tid < 128) {
        int o = tid >> 4, t = tid & 15;
        float a, b;
        resize_ab(o, t, 64.f, 1.f / 64.f, 0.70710678118654752f, a, b);
        tA512[o * 17 + t] = a;
        tB512[o * 17 + t] = b;
    } else if (tid < 256) {
        int q = tid - 128;
        int o = q >> 4, t = q & 15;
        float a, b;
        resize_ab(o, t, 32.f, 1.f / 32.f, 0.5f, a, b);
        tA256[o * 17 + t] = a;
        tB256[o * 17 + t] = b;
    }
}

__global__ void __launch_bounds__(256)
    k_fused(const float *__restrict__ x, const float *__restrict__ Wg,
            const float *__restrict__ bias, float *__restrict__ out) {
    __shared__ float tA512[8 * 17], tB512[8 * 17], tA256[8 * 17], tB256[8 * 17];
    __shared__ float sm[16 * 64];  // [W-block t][chunk c][16 partials]
    __shared__ float Vs[4096];     // out-stage: [16 blocks][8 mt][32 z]
    __shared__ float Ys[32 * 33];  // out-stage: combined Y
    __shared__ int sPg;

    const int tid = threadIdx.x;
    const int img = blockIdx.y, b = blockIdx.x;
    fill_tables(tid, tA512, tB512, tA256, tB256);

    const float4 *xp = reinterpret_cast<const float4 *>(
                           x + (((size_t)img << 20) + ((size_t)b << 16))) +
                       tid;

    float4 s1e = {0, 0, 0, 0}, s1o = {0, 0, 0, 0};
    float4 m1e = {0, 0, 0, 0}, m1o = {0, 0, 0, 0};
    float4 s1h = {0, 0, 0, 0}, m1h = {0, 0, 0, 0};

#pragma unroll
    for (int pp = 0; pp < 16; pp++) {
        float4 r0 = xp[(pp * 4 + 0) << 8];
        float4 r1 = xp[(pp * 4 + 1) << 8];
        float4 r2 = xp[(pp * 4 + 2) << 8];
        float4 r3 = xp[(pp * 4 + 3) << 8];
        const float p0 = (float)(2 * pp), p1 = (float)(2 * pp + 1);

#define COMP(f)                                      \
    {                                                \
        float lo0 = r0.f + r1.f, hi0 = r0.f - r1.f;  \
        float lo1 = r2.f + r3.f, hi1 = r2.f - r3.f;  \
        s1e.f += lo0;                                \
        m1e.f = fmaf(p0, lo0, m1e.f);                \
        s1o.f += lo1;                                \
        m1o.f = fmaf(p1, lo1, m1o.f);                \
        s1h.f += hi0 + hi1;                          \
        m1h.f = fmaf(p0, hi0, m1h.f);                \
        m1h.f = fmaf(p1, hi1, m1h.f);                \
    }
        COMP(x) COMP(y) COMP(z) COMP(w)
#undef COMP
    }

    // Derived H moments (exact): s2 == s1.
    float4 S1, M1, M2, S2H, M2H;
#define DRV(f)                        \
    {                                 \
        S1.f = s1e.f + s1o.f;         \
        M1.f = m1e.f + m1o.f;         \
        float tt = m1o.f - s1o.f;     \
        M2.f = 0.5f * (m1e.f + tt);   \
        M2H.f = 0.5f * (m1e.f - tt);  \
        S2H.f = s1e.f - s1o.f;        \
    }
    DRV(x) DRV(y) DRV(z) DRV(w)
#undef DRV

    // ---- W-axis epilogue ----
    const float u0 = (float)((2 * tid) & 31), u1 = u0 + 1.f;
    const float u2 = (float)(tid & 15);
    const int lane4 = tid & 15;
    float *smrow = sm + (tid >> 4) * 64;

#define CHUNK(c, A4, B4)                                                    \
    {                                                                       \
        float v[16];                                                        \
        {                                                                   \
            float l0 = A4.x + A4.y, h0 = A4.x - A4.y;                       \
            float l1 = A4.z + A4.w, h1 = A4.z - A4.w;                       \
            v[0] = l0 + l1;                                                 \
            v[1] = fmaf(u0, l0, u1 * l1);                                   \
            v[2] = h0 + h1;                                                 \
            v[3] = fmaf(u0, h0, u1 * h1);                                   \
            float lo2 = l0 + l1, hi2 = l0 - l1;                             \
            v[4] = lo2;                                                     \
            v[5] = u2 * lo2;                                                \
            v[6] = hi2;                                                     \
            v[7] = u2 * hi2;                                                \
        }                                                                   \
        {                                                                   \
            float l0 = B4.x + B4.y, h0 = B4.x - B4.y;                       \
            float l1 = B4.z + B4.w, h1 = B4.z - B4.w;                       \
            v[8] = l0 + l1;                                                 \
            v[9] = fmaf(u0, l0, u1 * l1);                                   \
            v[10] = h0 + h1;                                                \
            v[11] = fmaf(u0, h0, u1 * h1);                                  \
            float lo2 = l0 + l1, hi2 = l0 - l1;                             \
            v[12] = lo2;                                                    \
            v[13] = u2 * lo2;                                               \
            v[14] = hi2;                                                    \
            v[15] = u2 * hi2;                                               \
        }                                                                   \
        _Pragma("unroll") for (int d = 8; d >= 1; d >>= 1) {                \
            bool up = (tid & d) != 0;                                       \
            _Pragma("unroll") for (int i = 0; i < d; i++) {                 \
                float send = up ? v[i] : v[i + d];                          \
                float other = __shfl_xor_sync(FULLMASK, send, d);           \
                v[i] = (up ? v[i + d] : v[i]) + other;                      \
            }                                                               \
        }                                                                   \
        smrow[(c) * 16 + lane4] = v[0];                                     \
    }

    CHUNK(0, S1, M1)
    CHUNK(1, s1h, m1h)
    CHUNK(2, S1, M2)
    CHUNK(3, S2H, M2H)
#undef CHUNK

    __syncthreads();

    // Final combine -> g_V (streaming store; consumed once by the tail).
    {
        int mtH = tid >> 5, z = tid & 31, g = z >> 3, o = z & 7;
        const float *A = (g < 2) ? tA256 : tA512;
        const float *B = (g < 2) ? tB256 : tB512;
        int wb = (g & 2) ? ((g & 1) ? 2 : 0) : ((g & 1) ? 6 : 4);
        const float *base = sm + (mtH >> 1) * 16 + (mtH & 1) * 8 + wb;
        float acc = 0.f;
#pragma unroll
        for (int t = 0; t < 16; t++)
            acc = fmaf(A[o * 17 + t], base[t * 64],
                       fmaf(B[o * 17 + t], base[t * 64 + 1], acc));
        __stcs(&g_V[(((size_t)(img * 16 + b)) << 8) + tid], acc);
    }

    // ---- arrival detection: last FOUR blocks per image finish the image ----
    __threadfence();
    __syncthreads();
    if (tid == 0) {
        unsigned old = atomicAdd(&g_ctr[img], 1u);
        int pg = (int)(old & 15u) - 12;
        if (pg >= 0 && pg < 3) {
            // Ranks 12-14: wait until all 16 arrivals of this replay landed.
            unsigned target = (old | 15u) + 1u;
            while ((int)(atomicAdd(&g_ctr[img], 0u) - target) < 0)
                __nanosleep(64);
        }
        sPg = pg;
    }
    __syncthreads();
    if (sPg < 0) return;
    const int pg = sPg;
    __threadfence();

    // ---- output stage: this block computes Y and writes p = pg*16..+15 ----
    {
        const float4 *vg =
            reinterpret_cast<const float4 *>(g_V + ((size_t)img << 12));
        float4 *vs = reinterpret_cast<float4 *>(Vs);
#pragma unroll
        for (int i = 0; i < 4; i++) vs[tid + (i << 8)] = vg[tid + (i << 8)];
    }
    __syncthreads();

    // Y[ri][cb..cb+3]; row groups -> H moment types:
    // gr0->(s2,m2)@4 gr1->(s2h,m2h)@6 gr2->(s1,m1)@0 gr3->(s1h,m1h)@2
    {
        int ri = tid >> 3;
        int gr = ri >> 3, o = ri & 7;
        int cb = (tid & 7) << 2;
        const float *A = (gr < 2) ? tA256 : tA512;
        const float *B = (gr < 2) ? tB256 : tB512;
        int smt = ((gr < 2) ? 4 : 0) + ((gr & 1) << 1);
        float a0 = 0, a1 = 0, a2 = 0, a3 = 0;
#pragma unroll
        for (int t = 0; t < 16; t++) {
            float av = A[o * 17 + t], bv = B[o * 17 + t];
            const float *S = Vs + ((t << 3) + smt) * 32 + cb;
            const float *M = S + 32;
            a0 = fmaf(av, S[0], fmaf(bv, M[0], a0));
            a1 = fmaf(av, S[1], fmaf(bv, M[1], a1));
            a2 = fmaf(av, S[2], fmaf(bv, M[2], a2));
            a3 = fmaf(av, S[3], fmaf(bv, M[3], a3));
        }
        Ys[ri * 33 + cb + 0] = a0;
        Ys[ri * 33 + cb + 1] = a1;
        Ys[ri * 33 + cb + 2] = a2;
        Ys[ri * 33 + cb + 3] = a3;
    }
    __syncthreads();

    // (rowgroup,colgroup) map:
    // cA2(0,0) cH2(1,0) cV2(0,1) cD2(1,1) cH1(3,2) cV1(2,3) cD1(3,3)
    {
        float w0 = Wg[tid], w1 = Wg[256 + tid], w2 = Wg[512 + tid],
              w3 = Wg[768 + tid], w4 = Wg[1024 + tid], w5 = Wg[1280 + tid],
              w6 = Wg[1536 + tid];
        float bb = bias[tid];
        float *op = out + ((size_t)img << 14) + tid;
        const int pbase = pg << 4;
#pragma unroll
        for (int q = 0; q < 16; q++) {
            int p = pbase + q;
            int i = p >> 3, j = p & 7;
            float v = bb;
            v = fmaf(Ys[(0 + i) * 33 + (0 + j)], w0, v);
            v = fmaf(Ys[(8 + i) * 33 + (0 + j)], w1, v);
            v = fmaf(Ys[(0 + i) * 33 + (8 + j)], w2, v);
            v = fmaf(Ys[(8 + i) * 33 + (8 + j)], w3, v);
            v = fmaf(Ys[(24 + i) * 33 + (16 + j)], w4, v);
            v = fmaf(Ys[(16 + i) * 33 + (24 + j)], w5, v);
            v = fmaf(Ys[(24 + i) * 33 + (24 + j)], w6, v);
            __stcs(&op[(size_t)p << 8], v);
        }
    }
}

extern "C" void kernel_launch(void *const *d_in, const int *in_sizes, int n_in,
                              void *d_out, int out_size) {
    const float *x = (const float *)d_in[0];     // [64,1,1024,1024]
    const float *W = (const float *)d_in[1];     // [7,256]
    const float *bias = (const float *)d_in[2];  // [256]
    float *out = (float *)d_out;                 // [64,64,256]

    dim3 g(16, 64);
    k_fused<<<g, 256>>>(x, W, bias, out);
}

// round 16
// speedup vs baseline: 1.0138x; 1.0138x over previous
#include <cuda_runtime.h>

// ---------------------------------------------------------------------------
// WaveletEncoder: 2-level Haar wavedec2 -> bilinear(antialias) resize to 8x8
// -> stack 7 maps -> [B,64,7] @ W[7,256] + b.
//
// All-linear separable pipeline; axes commute; triangle antialias resize
// weight is linear within blocks of K/2 samples => per-block (sum, moment).
//
// CONVERGED FINAL (== R14, the best-measured config at 53.31us):
// kernel time == measured read floor (268MB at the chip's sustained
// ~5.4TB/s). Grid (16,64), one 64-row unit per block, flat fully-unrolled
// LDG.128 quads (default cache policy — g_V is re-read by the tail, so no
// evict-first hints); 6 H-axis accumulators {s1e,s1o,m1e,m1o,s1h,m1h};
// exact derived level-2 moments:
//   m2=(m1e+(m1o-s1o))/2, m2h=(m1e-(m1o-s1o))/2, s2h=s1e-s1o, s2=s1.
// W-axis Haar intra-thread -> 16 W-partials/chunk -> 16-lane butterfly ->
// smem -> 256-thread coefficient combine -> V[imgb][8][32]. The last FOUR
// arrivals per image (monotonic atomic counter, replay-safe) finish the
// image in parallel: ranks 12-14 spin briefly until all 16 arrivals, then
// each computes Y redundantly (bitwise identical) and writes its 16 of the
// 64 output positions. Fully deterministic output.
// ---------------------------------------------------------------------------

#define FULLMASK 0xffffffffu

__device__ float g_V[64u * 16u * 8u * 32u];  // 1 MB [imgb][8 mtH][32 z]
__device__ unsigned g_ctr[64];               // per-image arrival counters

static __device__ __forceinline__ void resize_ab(int o, int t, float K,
                                                 float invK, float fold,
                                                 float &a, float &b) {
    float tot = K * ((o == 0 || o == 7) ? 0.875f : 1.0f);
    float sf = (o + 0.5f) * K - 0.5f;
    float i0 = t * (K * 0.5f);
    float w0 = fmaxf(0.f, 1.f - fabsf(sf - i0) * invK);
    float w1 = fmaxf(0.f, 1.f - fabsf(sf - (i0 + 1.f)) * invK);
    float s = fold / tot;
    a = w0 * s;
    b = (w1 - w0) * s;
}

static __device__ __forceinline__ void fill_tables(int tid, float *tA512,
                                                   float *tB512, float *tA256,
                                                   float *tB256) {
    if (tid < 128) {
        int o = tid >> 4, t = tid & 15;
        float a, b;
        resize_ab(o, t, 64.f, 1.f / 64.f, 0.70710678118654752f, a, b);
        tA512[o * 17 + t] = a;
        tB512[o * 17 + t] = b;
    } else if (tid < 256) {
        int q = tid - 128;
        int o = q >> 4, t = q & 15;
        float a, b;
        resize_ab(o, t, 32.f, 1.f / 32.f, 0.5f, a, b);
        tA256[o * 17 + t] = a;
        tB256[o * 17 + t] = b;
    }
}

__global__ void __launch_bounds__(256)
    k_fused(const float *__restrict__ x, const float *__restrict__ Wg,
            const float *__restrict__ bias, float *__restrict__ out) {
    __shared__ float tA512[8 * 17], tB512[8 * 17], tA256[8 * 17], tB256[8 * 17];
    __shared__ float sm[16 * 64];  // [W-block t][chunk c][16 partials]
    __shared__ float Vs[4096];     // out-stage: [16 blocks][8 mt][32 z]
    __shared__ float Ys[32 * 33];  // out-stage: combined Y
    __shared__ int sPg;

    const int tid = threadIdx.x;
    const int img = blockIdx.y, b = blockIdx.x;
    fill_tables(tid, tA512, tB512, tA256, tB256);

    const float4 *xp = reinterpret_cast<const float4 *>(
                           x + (((size_t)img << 20) + ((size_t)b << 16))) +
                       tid;

    float4 s1e = {0, 0, 0, 0}, s1o = {0, 0, 0, 0};
    float4 m1e = {0, 0, 0, 0}, m1o = {0, 0, 0, 0};
    float4 s1h = {0, 0, 0, 0}, m1h = {0, 0, 0, 0};

#pragma unroll
    for (int pp = 0; pp < 16; pp++) {
        float4 r0 = xp[(pp * 4 + 0) << 8];
        float4 r1 = xp[(pp * 4 + 1) << 8];
        float4 r2 = xp[(pp * 4 + 2) << 8];
        float4 r3 = xp[(pp * 4 + 3) << 8];
        const float p0 = (float)(2 * pp), p1 = (float)(2 * pp + 1);

#define COMP(f)                                      \
    {                                                \
        float lo0 = r0.f + r1.f, hi0 = r0.f - r1.f;  \
        float lo1 = r2.f + r3.f, hi1 = r2.f - r3.f;  \
        s1e.f += lo0;                                \
        m1e.f = fmaf(p0, lo0, m1e.f);                \
        s1o.f += lo1;                                \
        m1o.f = fmaf(p1, lo1, m1o.f);                \
        s1h.f += hi0 + hi1;                          \
        m1h.f = fmaf(p0, hi0, m1h.f);                \
        m1h.f = fmaf(p1, hi1, m1h.f);                \
    }
        COMP(x) COMP(y) COMP(z) COMP(w)
#undef COMP
    }

    // Derived H moments (exact): s2 == s1.
    float4 S1, M1, M2, S2H, M2H;
#define DRV(f)                        \
    {                                 \
        S1.f = s1e.f + s1o.f;         \
        M1.f = m1e.f + m1o.f;         \
        float tt = m1o.f - s1o.f;     \
        M2.f = 0.5f * (m1e.f + tt);   \
        M2H.f = 0.5f * (m1e.f - tt);  \
        S2H.f = s1e.f - s1o.f;        \
    }
    DRV(x) DRV(y) DRV(z) DRV(w)
#undef DRV

    // ---- W-axis epilogue ----
    const float u0 = (float)((2 * tid) & 31), u1 = u0 + 1.f;
    const float u2 = (float)(tid & 15);
    const int lane4 = tid & 15;
    float *smrow = sm + (tid >> 4) * 64;

#define CHUNK(c, A4, B4)                                                    \
    {                                                                       \
        float v[16];                                                        \
        {                                                                   \
            float l0 = A4.x + A4.y, h0 = A4.x - A4.y;                       \
            float l1 = A4.z + A4.w, h1 = A4.z - A4.w;                       \
            v[0] = l0 + l1;                                                 \
            v[1] = fmaf(u0, l0, u1 * l1);                                   \
            v[2] = h0 + h1;                                                 \
            v[3] = fmaf(u0, h0, u1 * h1);                                   \
            float lo2 = l0 + l1, hi2 = l0 - l1;                             \
            v[4] = lo2;                                                     \
            v[5] = u2 * lo2;                                                \
            v[6] = hi2;                                                     \
            v[7] = u2 * hi2;                                                \
        }                                                                   \
        {                                                                   \
            float l0 = B4.x + B4.y, h0 = B4.x - B4.y;                       \
            float l1 = B4.z + B4.w, h1 = B4.z - B4.w;                       \
            v[8] = l0 + l1;                                                 \
            v[9] = fmaf(u0, l0, u1 * l1);                                   \
            v[10] = h0 + h1;                                                \
            v[11] = fmaf(u0, h0, u1 * h1);                                  \
            float lo2 = l0 + l1, hi2 = l0 - l1;                             \
            v[12] = lo2;                                                    \
            v[13] = u2 * lo2;                                               \
            v[14] = hi2;                                                    \
            v[15] = u2 * hi2;                                               \
        }                                                                   \
        _Pragma("unroll") for (int d = 8; d >= 1; d >>= 1) {                \
            bool up = (tid & d) != 0;                                       \
            _Pragma("unroll") for (int i = 0; i < d; i++) {                 \
                float send = up ? v[i] : v[i + d];                          \
                float other = __shfl_xor_sync(FULLMASK, send, d);           \
                v[i] = (up ? v[i + d] : v[i]) + other;                      \
            }                                                               \
        }                                                                   \
        smrow[(c) * 16 + lane4] = v[0];                                     \
    }

    CHUNK(0, S1, M1)
    CHUNK(1, s1h, m1h)
    CHUNK(2, S1, M2)
    CHUNK(3, S2H, M2H)
#undef CHUNK

    __syncthreads();

    // Final combine -> g_V. Thread = (mtH = tid>>5, z = tid&31), z = g*8+o.
    {
        int mtH = tid >> 5, z = tid & 31, g = z >> 3, o = z & 7;
        const float *A = (g < 2) ? tA256 : tA512;
        const float *B = (g < 2) ? tB256 : tB512;
        int wb = (g & 2) ? ((g & 1) ? 2 : 0) : ((g & 1) ? 6 : 4);
        const float *base = sm + (mtH >> 1) * 16 + (mtH & 1) * 8 + wb;
        float acc = 0.f;
#pragma unroll
        for (int t = 0; t < 16; t++)
            acc = fmaf(A[o * 17 + t], base[t * 64],
                       fmaf(B[o * 17 + t], base[t * 64 + 1], acc));
        g_V[(((size_t)(img * 16 + b)) << 8) + tid] = acc;
    }

    // ---- arrival detection: last FOUR blocks per image finish the image ----
    __threadfence();
    __syncthreads();
    if (tid == 0) {
        unsigned old = atomicAdd(&g_ctr[img], 1u);
        int pg = (int)(old & 15u) - 12;
        if (pg >= 0 && pg < 3) {
            // Ranks 12-14: wait until all 16 arrivals of this replay landed.
            unsigned target = (old | 15u) + 1u;
            while ((int)(atomicAdd(&g_ctr[img], 0u) - target) < 0)
                __nanosleep(64);
        }
        sPg = pg;
    }
    __syncthreads();
    if (sPg < 0) return;
    const int pg = sPg;
    __threadfence();

    // ---- output stage: this block computes Y and writes p = pg*16..+15 ----
    {
        const float4 *vg =
            reinterpret_cast<const float4 *>(g_V + ((size_t)img << 12));
        float4 *vs = reinterpret_cast<float4 *>(Vs);
#pragma unroll
        for (int i = 0; i < 4; i++) vs[tid + (i << 8)] = vg[tid + (i << 8)];
    }
    __syncthreads();

    // Y[ri][cb..cb+3]; row groups -> H moment types:
    // gr0->(s2,m2)@4 gr1->(s2h,m2h)@6 gr2->(s1,m1)@0 gr3->(s1h,m1h)@2
    {
        int ri = tid >> 3;
        int gr = ri >> 3, o = ri & 7;
        int cb = (tid & 7) << 2;
        const float *A = (gr < 2) ? tA256 : tA512;
        const float *B = (gr < 2) ? tB256 : tB512;
        int smt = ((gr < 2) ? 4 : 0) + ((gr & 1) << 1);
        float a0 = 0, a1 = 0, a2 = 0, a3 = 0;
#pragma unroll
        for (int t = 0; t < 16; t++) {
            float av = A[o * 17 + t], bv = B[o * 17 + t];
            const float *S = Vs + ((t << 3) + smt) * 32 + cb;
            const float *M = S + 32;
            a0 = fmaf(av, S[0], fmaf(bv, M[0], a0));
            a1 = fmaf(av, S[1], fmaf(bv, M[1], a1));
            a2 = fmaf(av, S[2], fmaf(bv, M[2], a2));
            a3 = fmaf(av, S[3], fmaf(bv, M[3], a3));
        }
        Ys[ri * 33 + cb + 0] = a0;
        Ys[ri * 33 + cb + 1] = a1;
        Ys[ri * 33 + cb + 2] = a2;
        Ys[ri * 33 + cb + 3] = a3;
    }
    __syncthreads();

    // (rowgroup,colgroup) map:
    // cA2(0,0) cH2(1,0) cV2(0,1) cD2(1,1) cH1(3,2) cV1(2,3) cD1(3,3)
    {
        float w0 = Wg[tid], w1 = Wg[256 + tid], w2 = Wg[512 + tid],
              w3 = Wg[768 + tid], w4 = Wg[1024 + tid], w5 = Wg[1280 + tid],
              w6 = Wg[1536 + tid];
        float bb = bias[tid];
        float *op = out + ((size_t)img << 14) + tid;
        const int pbase = pg << 4;
#pragma unroll
        for (int q = 0; q < 16; q++) {
            int p = pbase + q;
            int i = p >> 3, j = p & 7;
            float v = bb;
            v = fmaf(Ys[(0 + i) * 33 + (0 + j)], w0, v);
            v = fmaf(Ys[(8 + i) * 33 + (0 + j)], w1, v);
            v = fmaf(Ys[(0 + i) * 33 + (8 + j)], w2, v);
            v = fmaf(Ys[(8 + i) * 33 + (8 + j)], w3, v);
            v = fmaf(Ys[(24 + i) * 33 + (16 + j)], w4, v);
            v = fmaf(Ys[(16 + i) * 33 + (24 + j)], w5, v);
            v = fmaf(Ys[(24 + i) * 33 + (24 + j)], w6, v);
            op[(size_t)p << 8] = v;
        }
    }
}

extern "C" void kernel_launch(void *const *d_in, const int *in_sizes, int n_in,
                              void *d_out, int out_size) {
    const float *x = (const float *)d_in[0];     // [64,1,1024,1024]
    const float *W = (const float *)d_in[1];     // [7,256]
    const float *bias = (const float *)d_in[2];  // [256]
    float *out = (float *)d_out;                 // [64,64,256]

    dim3 g(16, 64);
    k_fused<<<g, 256>>>(x, W, bias, out);
}